// round 2
// baseline (speedup 1.0000x reference)
#include <cuda_runtime.h>
#include <math.h>

#define DIM   1024
#define BLOCK 1024
#define NWARP (BLOCK / 32)            // 32 warps
#define GRID  128
#define ROWS_PER_CTA (DIM / GRID)     // 8 rows per CTA
#define WARPS_PER_ROW (NWARP / ROWS_PER_CTA)  // 4 warps split K per row
// each warp covers 256 floats of K = 64 float4, i.e. 2 float4 per lane

__device__ float        g_z[DIM];
__device__ unsigned int g_count = 0;

__global__ __launch_bounds__(BLOCK, 1)
void embed_fused_kernel(const float* __restrict__ filters,
                        const float* __restrict__ w_t,
                        const float* __restrict__ w_h,
                        float*       __restrict__ out,
                        int vocab)
{
    __shared__ float s_y[DIM];
    __shared__ float s_pt[NWARP];     // per-warp partial dot (w_t)
    __shared__ float s_ph[NWARP];     // per-warp partial dot (w_h)
    __shared__ float s_red[NWARP];    // softmax reductions
    __shared__ float s_bcast[2];      // bmax, bsum
    __shared__ int   s_last;

    const int tid  = threadIdx.x;
    const int lane = tid & 31;
    const int warp = tid >> 5;

    const int row_local = warp >> 2;                      // 0..7
    const int kq        = warp & 3;                       // K-quarter 0..3
    const int row       = blockIdx.x * ROWS_PER_CTA + row_local;

    // ---- Issue the 8 MB weight stream FIRST (before the scattered gather) ---
    const float4* __restrict__ wt4 = (const float4*)(w_t + (size_t)row * DIM);
    const float4* __restrict__ wh4 = (const float4*)(w_h + (size_t)row * DIM);
    const int i0 = kq * 64 + lane;        // float4 index within the row
    const int i1 = i0 + 32;

    const float4 a0 = wt4[i0];
    const float4 a1 = wt4[i1];
    const float4 b0 = wh4[i0];
    const float4 b1 = wh4[i1];

    // ---- Scattered filter gather (overlaps with the stream above) ----------
    {
        float v = filters[(size_t)tid * (size_t)vocab];
        s_y[tid] = (tid == DIM - 1) ? v : fmaxf(v, 0.0f);
    }
    __syncthreads();

    // ---- Dot products -------------------------------------------------------
    const float4* __restrict__ y4 = (const float4*)s_y;
    const float4 y0 = y4[i0];
    const float4 y1 = y4[i1];

    float dt = a0.x * y0.x + a0.y * y0.y + a0.z * y0.z + a0.w * y0.w
             + a1.x * y1.x + a1.y * y1.y + a1.z * y1.z + a1.w * y1.w;
    float dh = b0.x * y0.x + b0.y * y0.y + b0.z * y0.z + b0.w * y0.w
             + b1.x * y1.x + b1.y * y1.y + b1.z * y1.z + b1.w * y1.w;

    #pragma unroll
    for (int o = 16; o > 0; o >>= 1) {
        dt += __shfl_xor_sync(0xffffffffu, dt, o);
        dh += __shfl_xor_sync(0xffffffffu, dh, o);
    }
    if (lane == 0) { s_pt[warp] = dt; s_ph[warp] = dh; }
    __syncthreads();

    // ---- Combine K-quarters, gate, write z ----------------------------------
    if (tid < ROWS_PER_CTA) {
        const int r = tid;
        float ft = 0.0f, fh = 0.0f;
        #pragma unroll
        for (int w = 0; w < WARPS_PER_ROW; ++w) {
            ft += s_pt[r * WARPS_PER_ROW + w];
            fh += s_ph[r * WARPS_PER_ROW + w];
        }
        const float t = 1.0f / (1.0f + expf(-ft));   // sigmoid
        const float g = fmaxf(fh, 0.0f);             // relu
        const int gr = blockIdx.x * ROWS_PER_CTA + r;
        g_z[gr] = t * g + (1.0f - t) * s_y[gr];
    }

    // ---- Last-CTA election --------------------------------------------------
    __threadfence();
    __syncthreads();
    if (tid == 0) {
        unsigned int ticket = atomicAdd(&g_count, 1u);
        s_last = (ticket == (unsigned int)(GRID - 1));
    }
    __syncthreads();
    if (!s_last) return;

    // ---- log_softmax over 1024 (1 element / thread) -------------------------
    const float v = __ldcg(&g_z[tid]);   // L2 read, bypass L1

    float lmax = v;
    #pragma unroll
    for (int o = 16; o > 0; o >>= 1)
        lmax = fmaxf(lmax, __shfl_xor_sync(0xffffffffu, lmax, o));
    if (lane == 0) s_red[warp] = lmax;
    __syncthreads();
    if (warp == 0) {
        float m = s_red[lane];
        #pragma unroll
        for (int o = 16; o > 0; o >>= 1)
            m = fmaxf(m, __shfl_xor_sync(0xffffffffu, m, o));
        if (lane == 0) s_bcast[0] = m;
    }
    __syncthreads();
    const float bmax = s_bcast[0];

    float e = expf(v - bmax);
    #pragma unroll
    for (int o = 16; o > 0; o >>= 1)
        e += __shfl_xor_sync(0xffffffffu, e, o);
    if (lane == 0) s_red[warp] = e;
    __syncthreads();
    if (warp == 0) {
        float s = s_red[lane];
        #pragma unroll
        for (int o = 16; o > 0; o >>= 1)
            s += __shfl_xor_sync(0xffffffffu, s, o);
        if (lane == 0) s_bcast[1] = s;
    }
    __syncthreads();

    out[tid] = v - bmax - logf(s_bcast[1]);

    if (tid == 0) g_count = 0;   // deterministic across graph replays
}

extern "C" void kernel_launch(void* const* d_in, const int* in_sizes, int n_in,
                              void* d_out, int out_size)
{
    const float* filters = (const float*)d_in[1];
    const float* w_t     = (const float*)d_in[2];
    const float* w_h     = (const float*)d_in[3];
    float*       out     = (float*)d_out;

    const int vocab = in_sizes[1] / DIM;   // 50257

    embed_fused_kernel<<<GRID, BLOCK>>>(filters, w_t, w_h, out, vocab);
}